// round 2
// baseline (speedup 1.0000x reference)
#include <cuda_runtime.h>

typedef unsigned long long ULL;

constexpr int B    = 512;
constexpr int T    = 2048;
constexpr int H    = 64;
constexpr int G    = 4 * H;   // 256 gates (i,f,g,o blocks of 64)
constexpr int NB   = 4;       // batch elements per block (2 f32x2 pairs)
constexpr int NBLK = B / NB;  // 128 blocks
constexpr int NTHR = G + 64;  // 256 gate threads + 2 layer-2 warps

__device__ __forceinline__ ULL pack2(float x, float y) {
    ULL r; asm("mov.b64 %0, {%1, %2};" : "=l"(r) : "f"(x), "f"(y)); return r;
}
__device__ __forceinline__ void unpack2(ULL v, float& x, float& y) {
    asm("mov.b64 {%0, %1}, %2;" : "=f"(x), "=f"(y) : "l"(v));
}
// Blackwell packed fp32 FMA: 2 results/instr at rt_SMSP=2 -> 128 FMA/SM/cyc
__device__ __forceinline__ ULL ffma2(ULL a, ULL b, ULL c) {
    ULL d; asm("fma.rn.f32x2 %0, %1, %2, %3;" : "=l"(d) : "l"(a), "l"(b), "l"(c)); return d;
}
// Accurate fast activations: ex2.approx (~2^-22 rel) + rcp.approx
__device__ __forceinline__ float fsigm(float x) {
    return __fdividef(1.f, 1.f + __expf(-x));
}
__device__ __forceinline__ float ftanh(float x) {
    return __fdividef(2.f, 1.f + __expf(-2.f * x)) - 1.f;
}

__global__ __launch_bounds__(NTHR, 1)
void lstm2_kernel(const float* __restrict__ x,
                  const float* __restrict__ Wih1,
                  const float* __restrict__ Whh1,
                  const float* __restrict__ bih1,
                  const float* __restrict__ bhh1,
                  const float* __restrict__ Wih2,
                  const float* __restrict__ Whh2,
                  const float* __restrict__ bih2,
                  const float* __restrict__ bhh2,
                  float* __restrict__ out)
{
    // 32KB: entire x for this block's 4 batch rows, interleaved for LDS.64 pairs
    __shared__ __align__(16) float xs[T][NB];
    __shared__ __align__(16) float h_sh[H][NB];      // h1 state, k-major x 4 batch
    __shared__ __align__(16) float gs[G][NB];        // activated gates
    __shared__ __align__(16) float c1buf[2][H][NB];  // double-buffered c1 for layer 2

    const int tid = threadIdx.x;
    const int b0  = blockIdx.x * NB;

    // ---- one-time preload ----
    #pragma unroll
    for (int bl = 0; bl < NB; bl++)
        for (int t = tid; t < T; t += NTHR)
            xs[t][bl] = x[(b0 + bl) * T + t];
    for (int i = tid; i < H * NB; i += NTHR)
        (&h_sh[0][0])[i] = 0.f;

    const bool is_gate = tid < G;

    // gate-thread persistent state: packed recurrent weights in registers
    ULL ww[H];
    ULL wxp = 0, bp = 0;
    float c1s0 = 0.f, c1s1 = 0.f, c1s2 = 0.f, c1s3 = 0.f;
    if (is_gate) {
        const int g = tid;
        #pragma unroll
        for (int k = 0; k < H; k++) {
            float w = Whh1[g * H + k];
            ww[k] = pack2(w, w);
        }
        float wi = Wih1[g];
        wxp = pack2(wi, wi);
        float bb = bih1[g] + bhh1[g];
        bp = pack2(bb, bb);
    }

    // layer-2 thread state (tid in [256,320)): (bl, gate q, k-segment of 16)
    float w2[16];
    float whh2q = 0.f, b2q = 0.f, h2 = 0.f, c2 = 0.f;
    const int l = tid - G;
    int bl2 = 0, ks = 0;
    if (!is_gate) {
        bl2 = l >> 4;
        const int q = (l >> 2) & 3;
        ks = (l & 3) * 16;
        #pragma unroll
        for (int j = 0; j < 16; j++) w2[j] = Wih2[q * H + ks + j];
        whh2q = Whh2[q];
        b2q   = bih2[q] + bhh2[q];
    }
    __syncthreads();

    for (int t = 0; t <= T; t++) {
        // ---------- phase A: layer-1 gates (t) || layer-2 (t-1) ----------
        if (is_gate) {
            if (t < T) {
                const int g = tid;
                ULL xp01 = *reinterpret_cast<const ULL*>(&xs[t][0]);
                ULL xp23 = *reinterpret_cast<const ULL*>(&xs[t][2]);
                ULL acc0 = ffma2(wxp, xp01, bp);
                ULL acc1 = ffma2(wxp, xp23, bp);
                #pragma unroll
                for (int k = 0; k < H; k++) {
                    ulonglong2 hv = *reinterpret_cast<const ulonglong2*>(&h_sh[k][0]);
                    acc0 = ffma2(ww[k], hv.x, acc0);
                    acc1 = ffma2(ww[k], hv.y, acc1);
                }
                float v0, v1, v2, v3;
                unpack2(acc0, v0, v1);
                unpack2(acc1, v2, v3);
                if ((g >> 6) == 2) { // g-gate block -> tanh
                    v0 = ftanh(v0); v1 = ftanh(v1); v2 = ftanh(v2); v3 = ftanh(v3);
                } else {             // i, f, o -> sigmoid
                    v0 = fsigm(v0); v1 = fsigm(v1); v2 = fsigm(v2); v3 = fsigm(v3);
                }
                *reinterpret_cast<float4*>(&gs[g][0]) = make_float4(v0, v1, v2, v3);
            }
        } else if (t > 0) {
            // layer 2 consumes c1 of step t-1 (pipelined one step behind)
            const float* cb = &c1buf[(t + 1) & 1][0][0];
            float s = 0.f;
            #pragma unroll
            for (int j = 0; j < 16; j++)
                s = fmaf(cb[(ks + j) * NB + bl2], w2[j], s);
            s += __shfl_xor_sync(0xffffffffu, s, 1);
            s += __shfl_xor_sync(0xffffffffu, s, 2);
            const float gate = s + b2q + h2 * whh2q;
            const int lane = l & 31;
            const int base = lane & 16;
            const float gi = __shfl_sync(0xffffffffu, gate, base + 0);
            const float gf = __shfl_sync(0xffffffffu, gate, base + 4);
            const float gg = __shfl_sync(0xffffffffu, gate, base + 8);
            const float go = __shfl_sync(0xffffffffu, gate, base + 12);
            c2 = fsigm(gf) * c2 + fsigm(gi) * ftanh(gg);
            h2 = fsigm(go) * ftanh(c2);
            if ((lane & 15) == 0)
                out[(b0 + bl2) * T + (t - 1)] = c2;
        }
        __syncthreads();
        // ---------- phase B: h1/c1 state update ----------
        if (tid < H && t < T) {
            const int j = tid;
            float4 gi4 = *reinterpret_cast<const float4*>(&gs[j][0]);
            float4 gf4 = *reinterpret_cast<const float4*>(&gs[H + j][0]);
            float4 gg4 = *reinterpret_cast<const float4*>(&gs[2 * H + j][0]);
            float4 go4 = *reinterpret_cast<const float4*>(&gs[3 * H + j][0]);
            float c0 = fmaf(gf4.x, c1s0, gi4.x * gg4.x);
            float c1_ = fmaf(gf4.y, c1s1, gi4.y * gg4.y);
            float cc = fmaf(gf4.z, c1s2, gi4.z * gg4.z);
            float c3 = fmaf(gf4.w, c1s3, gi4.w * gg4.w);
            c1s0 = c0; c1s1 = c1_; c1s2 = cc; c1s3 = c3;
            float4 hn = make_float4(go4.x * ftanh(c0), go4.y * ftanh(c1_),
                                    go4.z * ftanh(cc), go4.w * ftanh(c3));
            *reinterpret_cast<float4*>(&h_sh[j][0]) = hn;
            *reinterpret_cast<float4*>(&c1buf[t & 1][j][0]) =
                make_float4(c0, c1_, cc, c3);
        }
        __syncthreads();
    }
}

extern "C" void kernel_launch(void* const* d_in, const int* in_sizes, int n_in,
                              void* d_out, int out_size) {
    (void)in_sizes; (void)n_in; (void)out_size;
    lstm2_kernel<<<NBLK, NTHR>>>(
        (const float*)d_in[0],  // x
        (const float*)d_in[1],  // Wih1
        (const float*)d_in[2],  // Whh1
        (const float*)d_in[3],  // bih1
        (const float*)d_in[4],  // bhh1
        (const float*)d_in[5],  // Wih2
        (const float*)d_in[6],  // Whh2
        (const float*)d_in[7],  // bih2
        (const float*)d_in[8],  // bhh2
        (float*)d_out);
}